// round 15
// baseline (speedup 1.0000x reference)
#include <cuda_runtime.h>
#include <cuda_fp16.h>
#include <cstdint>

// Problem constants
#define B_    16
#define CIN_  256
#define T_    4096
#define N_    64
#define GC_   224
#define EC_   256
#define H_    8
#define HC_   32
#define COUT_ 256

// Scratch (no cudaMalloc allowed)
__device__ __half d_xt[(size_t)B_ * T_ * CIN_];       // x^T as fp16 [b][t][ci] (32 MB)
__device__ uint32_t d_wfrag[3 * 16 * 16 * 128];       // fp16x2 A-frags, conv
__device__ uint32_t d_gfrag[16 * 8 * 4 * 2 * 128];    // fp16x2 A-frags, attn
__device__ int    d_mask_kind;                        // 0=int32, 1=float32, 2=byte

// ---------------------------------------------------------------------------
// Helpers (base sm_100-legal: mma.sync sm_80+, ldmatrix sm_75+, cp.async sm_80+)
// ---------------------------------------------------------------------------
__device__ __forceinline__ uint32_t smem_u32(const void* p) {
    uint32_t a;
    asm("{ .reg .u64 t; cvta.to.shared.u64 t, %1; cvt.u32.u64 %0, t; }"
        : "=r"(a) : "l"(p));
    return a;
}
__device__ __forceinline__ uint32_t pack_h2(float lo, float hi) {
    __half2 h = __floats2half2_rn(lo, hi);   // .x = lo (lower 16 bits)
    return *(uint32_t*)&h;
}
__device__ __forceinline__ void ldsm_x2(uint32_t* r, uint32_t addr) {
    asm volatile("ldmatrix.sync.aligned.m8n8.x2.shared.b16 {%0, %1}, [%2];"
                 : "=r"(r[0]), "=r"(r[1]) : "r"(addr));
}
__device__ __forceinline__ void ldsm_x4(uint32_t* r, uint32_t addr) {
    asm volatile("ldmatrix.sync.aligned.m8n8.x4.shared.b16 {%0, %1, %2, %3}, [%4];"
                 : "=r"(r[0]), "=r"(r[1]), "=r"(r[2]), "=r"(r[3]) : "r"(addr));
}
__device__ __forceinline__ void mma_f16(float* d, const uint32_t* a, const uint32_t* b) {
    asm volatile(
        "mma.sync.aligned.m16n8k16.row.col.f32.f16.f16.f32 "
        "{%0,%1,%2,%3}, {%4,%5,%6,%7}, {%8,%9}, {%0,%1,%2,%3};"
        : "+f"(d[0]), "+f"(d[1]), "+f"(d[2]), "+f"(d[3])
        : "r"(a[0]), "r"(a[1]), "r"(a[2]), "r"(a[3]), "r"(b[0]), "r"(b[1]));
}
// cp.async 16B with zero-fill when invalid (src-size = 0)
__device__ __forceinline__ void cp16z(uint32_t dst, const void* src, bool valid) {
    int sz = valid ? 16 : 0;
    asm volatile("cp.async.cg.shared.global [%0], [%1], 16, %2;"
                 :: "r"(dst), "l"(src), "r"(sz) : "memory");
}
#define CP_COMMIT() asm volatile("cp.async.commit_group;" ::: "memory")
#define CP_WAIT(n)  asm volatile("cp.async.wait_group %0;" :: "n"(n) : "memory")

// Swizzled 512B-row tile (32 groups of 16B per row): logical group g stored at
// (g&24) | ((g&7) ^ (r&7)).
__device__ __forceinline__ uint32_t swz512(int r, int g) {
    return (uint32_t)(r * 512 + (((g & 24) | ((g & 7) ^ (r & 7))) << 4));
}

__device__ __forceinline__ float mask_at(const void* mp, int kind, int b, int t)
{
    size_t idx = (size_t)b * T_ + t;
    if (kind == 0)      return ((const int*)mp)[idx]   != 0   ? 1.f : 0.f;
    else if (kind == 1) return ((const float*)mp)[idx] != 0.f ? 1.f : 0.f;
    else                return ((const unsigned char*)mp)[idx] ? 1.f : 0.f;
}

// ---------------------------------------------------------------------------
// Kernel P1: role-dispatched prep: wfrag pack (blocks 0..47) + xt (rest)
// ---------------------------------------------------------------------------
#define P1_XT0 48
__global__ __launch_bounds__(256) void prep1_kernel(
    const float* __restrict__ x, const float* __restrict__ pw)
{
    __shared__ float s[32][33];
    const int bid = blockIdx.x, tid = threadIdx.x;

    if (bid < 48) {
        // ---- wfrag pack (proven R10) ----
        const int cog = bid & 15, tap = bid >> 4;
        for (int i = tid; i < 512; i += 256) {
            int kc = i >> 5, lane = i & 31;
            int m = cog * 16 + (lane >> 2);
            int k = kc * 16 + (lane & 3) * 2;
            uint32_t* dst = &d_wfrag[((size_t)(tap * 16 + cog) * 16 + kc) * 128 + lane * 4];
            dst[0] = pack_h2(pw[(size_t)(m * 256 + k) * 3 + tap],
                             pw[(size_t)(m * 256 + k + 1) * 3 + tap]);
            dst[1] = pack_h2(pw[(size_t)((m + 8) * 256 + k) * 3 + tap],
                             pw[(size_t)((m + 8) * 256 + k + 1) * 3 + tap]);
            dst[2] = pack_h2(pw[(size_t)(m * 256 + k + 8) * 3 + tap],
                             pw[(size_t)(m * 256 + k + 9) * 3 + tap]);
            dst[3] = pack_h2(pw[(size_t)((m + 8) * 256 + k + 8) * 3 + tap],
                             pw[(size_t)((m + 8) * 256 + k + 9) * 3 + tap]);
        }
    } else {
        // ---- xt transpose + fp16 convert (proven R10) ----
        const int xb = bid - P1_XT0;           // 0 .. 16383
        const int b = xb >> 10;
        const int ci0 = ((xb & 1023) >> 7) * 32;
        const int t0 = ((xb & 127)) * 32;
        const int tx = tid & 31, ty = tid >> 5;
#pragma unroll
        for (int k = 0; k < 4; k++)
            s[ty + 8 * k][tx] = x[((size_t)(b * CIN_ + ci0 + ty + 8 * k)) * T_ + t0 + tx];
        __syncthreads();
#pragma unroll
        for (int k = 0; k < 4; k++)
            d_xt[((size_t)b * T_ + t0 + ty + 8 * k) * CIN_ + ci0 + tx] =
                __float2half_rn(s[tx][ty + 8 * k]);
    }
}

// ---------------------------------------------------------------------------
// Kernel P2: guide FC + fused gfrag packing (proven R11)
// ---------------------------------------------------------------------------
__global__ __launch_bounds__(256) void prep2_kernel(
    const float* __restrict__ guide, const float* __restrict__ gw,
    const float* __restrict__ gb)
{
    const int b  = blockIdx.y;
    const int n0 = blockIdx.x * 8;
    const int e  = threadIdx.x;

    __shared__ float s_guide[8 * GC_];
    __shared__ float s_gw[256 * 33];
    __shared__ float s_g[8][256];

    for (int i = threadIdx.x; i < 8 * GC_; i += 256) {
        int nn = i / GC_, k = i % GC_;
        s_guide[i] = guide[((size_t)(b * N_ + n0 + nn)) * GC_ + k];
    }

    float acc[8];
#pragma unroll
    for (int nn = 0; nn < 8; nn++) acc[nn] = 0.f;

    for (int k0 = 0; k0 < GC_; k0 += 32) {
        __syncthreads();
        for (int i = threadIdx.x; i < 256 * 32; i += 256) {
            int ee = i >> 5, j = i & 31;
            s_gw[ee * 33 + j] = gw[ee * GC_ + k0 + j];
        }
        __syncthreads();
#pragma unroll
        for (int j = 0; j < 32; j++) {
            float w = s_gw[e * 33 + j];
#pragma unroll
            for (int nn = 0; nn < 8; nn++)
                acc[nn] += s_guide[nn * GC_ + k0 + j] * w;
        }
    }

    const float bias = gb[e];
#pragma unroll
    for (int nn = 0; nn < 8; nn++) s_g[nn][e] = acc[nn] + bias;
    __syncthreads();

    const int mg = n0 >> 4;
    const int rbase = (n0 & 8) ? 1 : 0;      // regs {1,3} vs {0,2}
    for (int i = threadIdx.x; i < 512; i += 256) {
        int h = i >> 6, kc = (i >> 5) & 1, lane = i & 31;
        int nn = (lane >> 2);
        int ee = h * 32 + kc * 16 + (lane & 3) * 2;
        uint32_t* dst = &d_gfrag[(((size_t)(b * 8 + h) * 4 + mg) * 2 + kc) * 128 + lane * 4];
        dst[rbase]     = pack_h2(s_g[nn][ee],     s_g[nn][ee + 1]);
        dst[rbase + 2] = pack_h2(s_g[nn][ee + 8], s_g[nn][ee + 9]);
    }
}

// ---------------------------------------------------------------------------
// Kernel P3: mask classify (proven; tiny, keeps conv as launch #4 for ncu)
// ---------------------------------------------------------------------------
__global__ void prep3_kernel(const uint4* __restrict__ m16, int n16)
{
    __shared__ int s_c0, s_c23;
    if (threadIdx.x == 0) { s_c0 = 0; s_c23 = 0; }
    __syncthreads();
    int c0 = 0, c23 = 0;
    for (int i = threadIdx.x; i < n16; i += blockDim.x) {
        uint4 v = m16[i];
        uint32_t ws[4] = { v.x, v.y, v.z, v.w };
#pragma unroll
        for (int k = 0; k < 4; k++) {
            if (ws[k] & 0x000000FFu) c0++;
            if (ws[k] & 0xFFFF0000u) c23++;
        }
    }
    atomicAdd(&s_c0, c0);
    atomicAdd(&s_c23, c23);
    __syncthreads();
    if (threadIdx.x == 0) {
        int kind;
        if (s_c0 > 0 && s_c23 == 0) kind = 0;
        else if (s_c0 == 0 && s_c23 > 0) kind = 1;
        else kind = 2;
        d_mask_kind = kind;
    }
}

// ---------------------------------------------------------------------------
// Kernel C: fused conv1d(k=3) + max-sigmoid attention, fp16 m16n8k16.
// CTA = 128 co x 128 t. Warp tile = 64 co x 32 t (8 warps = 2 cog x 4 tg):
// each B-fragment pair feeds 4 A-fragments (ldsm:mma halved vs R13).
// kc16 body is B-first (24 B-regs) then per-tap A loads (16 regs live).
// Each warp computes attn for its TWO heads (2cog, 2cog+1) over its 32 t.
// ---------------------------------------------------------------------------
#define CONV_ROWS   130
#define CONV_TILE_B (CONV_ROWS * 512)   // 66560 B

__global__ __launch_bounds__(256, 2) void conv_mma_kernel(
    const float* __restrict__ pb, const void* __restrict__ mask,
    const float* __restrict__ abias, float* __restrict__ out)
{
    extern __shared__ __align__(16) char s_dyn[];
    const int b = blockIdx.z, co0 = blockIdx.y * 128, t0 = blockIdx.x * 128;
    const int tid = threadIdx.x, w = tid >> 5, lane = tid & 31;
    const int cog = w & 1, tg = w >> 1;      // 2 cog x 4 tg
    const uint32_t smb = smem_u32(s_dyn);
    const __half* xtb = d_xt + (size_t)b * T_ * CIN_;

    // ---- stage half A (ci 0..127, groups 0..15) ----
#pragma unroll
    for (int it = 0; it < 9; it++) {
        int idx = tid + it * 256;            // 2080 x 16B
        if (it < 8 || idx < 2080) {
            int r = idx >> 4, g = idx & 15;
            int gt = t0 - 1 + r;
            int gtc = gt < 0 ? 0 : (gt >= T_ ? T_ - 1 : gt);
            cp16z(smb + swz512(r, g), xtb + (size_t)gtc * 256 + g * 8,
                  gt >= 0 && gt < T_);
        }
    }
    CP_COMMIT();
    // ---- stage half B (ci 128..255, groups 16..31) ----
#pragma unroll
    for (int it = 0; it < 9; it++) {
        int idx = tid + it * 256;
        if (it < 8 || idx < 2080) {
            int r = idx >> 4, g = 16 + (idx & 15);
            int gt = t0 - 1 + r;
            int gtc = gt < 0 ? 0 : (gt >= T_ ? T_ - 1 : gt);
            cp16z(smb + swz512(r, g), xtb + (size_t)gtc * 256 + g * 8,
                  gt >= 0 && gt < T_);
        }
    }
    CP_COMMIT();

    float acc[4][4][4];
#pragma unroll
    for (int mf = 0; mf < 4; mf++)
#pragma unroll
        for (int nt = 0; nt < 4; nt++)
#pragma unroll
            for (int r = 0; r < 4; r++) acc[mf][nt][r] = 0.f;

    const int lane7 = lane & 7;
    const int k_q   = (lane >> 3) & 1;   // x4: q&1 (k-group); also x2 matrix sel
    const int s_q   = (lane >> 4) & 1;   // x4: q>>1 (tap 0/1)

    // ---- compute: two K-halves, pipelined against staging ----
#pragma unroll
    for (int half = 0; half < 2; half++) {
        if (half == 0) { CP_WAIT(1); } else { CP_WAIT(0); }
        __syncthreads();
#pragma unroll 4
        for (int kcl = 0; kcl < 8; kcl++) {
            const int kc16 = half * 8 + kcl;
            // ---- B first: 4 nt x {x4 (taps 0,1) + x2 (tap 2)} = 24 regs ----
            uint32_t bfr[4][6];
            {
                uint32_t a4 = smb + swz512(tg * 32 + s_q + lane7, kc16 * 2 + k_q);
                uint32_t a2 = smb + swz512(tg * 32 + 2 + lane7,   kc16 * 2 + k_q);
#pragma unroll
                for (int nt = 0; nt < 4; nt++) {
                    ldsm_x4(bfr[nt], a4);        // {t0k0, t0k1, t1k0, t1k1}
                    ldsm_x2(bfr[nt] + 4, a2);    // {t2k0, t2k1}
                    a4 += 4096; a2 += 4096;
                }
            }
            // ---- per-tap A loads (16 regs live), then MMAs ----
#pragma unroll
            for (int tap = 0; tap < 3; tap++) {
                uint32_t afr[4][4];
#pragma unroll
                for (int mf = 0; mf < 4; mf++) {
                    const int cog16 = blockIdx.y * 8 + cog * 4 + mf;
                    const uint4 v = *(const uint4*)&d_wfrag[((size_t)(tap * 16 + cog16) * 16 + kc16) * 128 + lane * 4];
                    afr[mf][0] = v.x; afr[mf][1] = v.y;
                    afr[mf][2] = v.z; afr[mf][3] = v.w;
                }
#pragma unroll
                for (int nt = 0; nt < 4; nt++)
#pragma unroll
                    for (int mf = 0; mf < 4; mf++)
                        mma_f16(acc[mf][nt], afr[mf], bfr[nt] + 2 * tap);
            }
        }
    }

    // ---- attention for this warp's TWO heads (tile fully resident) ----
    float attn0[2][4], attn1[2][4];
#pragma unroll
    for (int hh = 0; hh < 2; hh++) {
        const int hw = blockIdx.y * 4 + cog * 2 + hh;
        const float ab = abias[hw];
#pragma unroll
        for (int nt = 0; nt < 4; nt++) {
            float a4v[4][4];
#pragma unroll
            for (int mg = 0; mg < 4; mg++)
#pragma unroll
                for (int r = 0; r < 4; r++) a4v[mg][r] = 0.f;
#pragma unroll
            for (int kca = 0; kca < 2; kca++) {
                const int kc16 = hw * 2 + kca;
                const int gk = kc16 * 2 + k_q;
                const int r = 1 + tg * 32 + nt * 8 + lane7;
                uint32_t bfr[2];
                ldsm_x2(bfr, smb + swz512(r, gk));
#pragma unroll
                for (int mg = 0; mg < 4; mg++) {
                    const uint4 v = *(const uint4*)&d_gfrag[(((size_t)(b * 8 + hw) * 4 + mg) * 2 + kca) * 128 + lane * 4];
                    uint32_t gfr[4] = { v.x, v.y, v.z, v.w };
                    mma_f16(a4v[mg], gfr, bfr);
                }
            }
            float m0 = -1e30f, m1 = -1e30f;
#pragma unroll
            for (int mg = 0; mg < 4; mg++) {
                m0 = fmaxf(m0, fmaxf(a4v[mg][0], a4v[mg][2]));
                m1 = fmaxf(m1, fmaxf(a4v[mg][1], a4v[mg][3]));
            }
#pragma unroll
            for (int d = 4; d <= 16; d <<= 1) {
                m0 = fmaxf(m0, __shfl_xor_sync(0xffffffffu, m0, d));
                m1 = fmaxf(m1, __shfl_xor_sync(0xffffffffu, m1, d));
            }
            float z0 = m0 * 0.17677669529663687f + ab;
            float z1 = m1 * 0.17677669529663687f + ab;
            attn0[hh][nt] = 1.f / (1.f + __expf(-z0));
            attn1[hh][nt] = 1.f / (1.f + __expf(-z1));
        }
    }

    // ---- epilogue: (+pb) * attn * mask ----
    const int mk = d_mask_kind;
#pragma unroll
    for (int mf = 0; mf < 4; mf++) {
        const int hh = mf >> 1;              // heads: mf 0,1 -> hh 0; mf 2,3 -> hh 1
        const int cob = co0 + cog * 64 + mf * 16 + (lane >> 2);
        const float bias0 = pb[cob], bias1 = pb[cob + 8];
        float* o0 = out + ((size_t)(b * 256 + cob)) * T_;
        float* o1 = o0 + (size_t)8 * T_;
#pragma unroll
        for (int nt = 0; nt < 4; nt++) {
            const int t = t0 + tg * 32 + nt * 8 + 2 * (lane & 3);
            float m0 = mask_at(mask, mk, b, t);
            float m1 = mask_at(mask, mk, b, t + 1);
            float2 v0, v1;
            v0.x = (acc[mf][nt][0] + bias0) * attn0[hh][nt] * m0;
            v0.y = (acc[mf][nt][1] + bias0) * attn1[hh][nt] * m1;
            v1.x = (acc[mf][nt][2] + bias1) * attn0[hh][nt] * m0;
            v1.y = (acc[mf][nt][3] + bias1) * attn1[hh][nt] * m1;
            *(float2*)(o0 + t) = v0;
            *(float2*)(o1 + t) = v1;
        }
    }
}

// ---------------------------------------------------------------------------
extern "C" void kernel_launch(void* const* d_in, const int* in_sizes, int n_in,
                              void* d_out, int out_size)
{
    const float* x     = (const float*)d_in[0];
    const float* guide = (const float*)d_in[1];
    const void*  mask  = (const void*)d_in[2];
    const float* gw    = (const float*)d_in[3];
    const float* gb    = (const float*)d_in[4];
    const float* abias = (const float*)d_in[5];
    const float* pw    = (const float*)d_in[6];
    const float* pb    = (const float*)d_in[7];
    float*       out   = (float*)d_out;

    static int attr_done = 0;
    if (!attr_done) {
        cudaFuncSetAttribute(conv_mma_kernel,
                             cudaFuncAttributeMaxDynamicSharedMemorySize, CONV_TILE_B);
        attr_done = 1;
    }

    prep1_kernel<<<P1_XT0 + 16384, 256>>>(x, pw);
    prep2_kernel<<<dim3(N_ / 8, B_), 256>>>(guide, gw, gb);
    prep3_kernel<<<1, 256>>>((const uint4*)mask, in_sizes[2] / 16);
    conv_mma_kernel<<<dim3(T_ / 128, COUT_ / 128, B_), 256, CONV_TILE_B>>>(pb, mask, abias, out);
}

// round 16
// speedup vs baseline: 1.2596x; 1.2596x over previous
#include <cuda_runtime.h>
#include <cuda_fp16.h>
#include <cstdint>

// Problem constants
#define B_    16
#define CIN_  256
#define T_    4096
#define N_    64
#define GC_   224
#define EC_   256
#define H_    8
#define HC_   32
#define COUT_ 256

// Scratch (no cudaMalloc allowed)
__device__ __half d_xt[(size_t)B_ * T_ * CIN_];       // x^T as fp16 [b][t][ci] (32 MB)
__device__ uint32_t d_wfrag[3 * 16 * 16 * 128];       // fp16x2 A-frags, conv
__device__ uint32_t d_gfrag[16 * 8 * 4 * 2 * 128];    // fp16x2 A-frags, attn
__device__ int    d_mask_kind;                        // 0=int32, 1=float32, 2=byte

// ---------------------------------------------------------------------------
// Helpers (base sm_100-legal: mma.sync sm_80+, ldmatrix sm_75+, cp.async sm_80+)
// ---------------------------------------------------------------------------
__device__ __forceinline__ uint32_t smem_u32(const void* p) {
    uint32_t a;
    asm("{ .reg .u64 t; cvta.to.shared.u64 t, %1; cvt.u32.u64 %0, t; }"
        : "=r"(a) : "l"(p));
    return a;
}
__device__ __forceinline__ uint32_t pack_h2(float lo, float hi) {
    __half2 h = __floats2half2_rn(lo, hi);   // .x = lo (lower 16 bits)
    return *(uint32_t*)&h;
}
__device__ __forceinline__ void ldsm_x2(uint32_t* r, uint32_t addr) {
    asm volatile("ldmatrix.sync.aligned.m8n8.x2.shared.b16 {%0, %1}, [%2];"
                 : "=r"(r[0]), "=r"(r[1]) : "r"(addr));
}
__device__ __forceinline__ void ldsm_x4(uint32_t* r, uint32_t addr) {
    asm volatile("ldmatrix.sync.aligned.m8n8.x4.shared.b16 {%0, %1, %2, %3}, [%4];"
                 : "=r"(r[0]), "=r"(r[1]), "=r"(r[2]), "=r"(r[3]) : "r"(addr));
}
__device__ __forceinline__ void mma_f16(float* d, const uint32_t* a, const uint32_t* b) {
    asm volatile(
        "mma.sync.aligned.m16n8k16.row.col.f32.f16.f16.f32 "
        "{%0,%1,%2,%3}, {%4,%5,%6,%7}, {%8,%9}, {%0,%1,%2,%3};"
        : "+f"(d[0]), "+f"(d[1]), "+f"(d[2]), "+f"(d[3])
        : "r"(a[0]), "r"(a[1]), "r"(a[2]), "r"(a[3]), "r"(b[0]), "r"(b[1]));
}
// cp.async 16B with zero-fill when invalid (src-size = 0)
__device__ __forceinline__ void cp16z(uint32_t dst, const void* src, bool valid) {
    int sz = valid ? 16 : 0;
    asm volatile("cp.async.cg.shared.global [%0], [%1], 16, %2;"
                 :: "r"(dst), "l"(src), "r"(sz) : "memory");
}
#define CP_COMMIT() asm volatile("cp.async.commit_group;" ::: "memory")
#define CP_WAIT(n)  asm volatile("cp.async.wait_group %0;" :: "n"(n) : "memory")

// Swizzled 512B-row tile (32 groups of 16B per row): logical group g stored at
// (g&24) | ((g&7) ^ (r&7)).
__device__ __forceinline__ uint32_t swz512(int r, int g) {
    return (uint32_t)(r * 512 + (((g & 24) | ((g & 7) ^ (r & 7))) << 4));
}

__device__ __forceinline__ float mask_at(const void* mp, int kind, int b, int t)
{
    size_t idx = (size_t)b * T_ + t;
    if (kind == 0)      return ((const int*)mp)[idx]   != 0   ? 1.f : 0.f;
    else if (kind == 1) return ((const float*)mp)[idx] != 0.f ? 1.f : 0.f;
    else                return ((const unsigned char*)mp)[idx] ? 1.f : 0.f;
}

// ---------------------------------------------------------------------------
// Kernel P: ALL prep in one launch, role-dispatched by blockIdx.x:
//   bid 0         : mask classify           (proven)
//   bid 1..48     : wfrag pack              (proven)
//   bid 49..176   : guide FC + gfrag pack   (proven logic; smem 32 KB dyn)
//   bid 177..     : xt transpose + fp16     (proven)
// Dynamic smem (32 KB) is overlaid per role.
// ---------------------------------------------------------------------------
#define P_GF0 49
#define P_XT0 177
__global__ __launch_bounds__(256) void prep_kernel(
    const float* __restrict__ x, const float* __restrict__ pw,
    const float* __restrict__ guide, const float* __restrict__ gw,
    const float* __restrict__ gb,
    const uint4* __restrict__ m16, int n16)
{
    extern __shared__ __align__(16) float dynf[];
    const int bid = blockIdx.x, tid = threadIdx.x;

    if (bid == 0) {
        // ---- mask classify ----
        __shared__ int s_c0, s_c23;
        if (tid == 0) { s_c0 = 0; s_c23 = 0; }
        __syncthreads();
        int c0 = 0, c23 = 0;
        for (int i = tid; i < n16; i += 256) {
            uint4 v = m16[i];
            uint32_t ws[4] = { v.x, v.y, v.z, v.w };
#pragma unroll
            for (int k = 0; k < 4; k++) {
                if (ws[k] & 0x000000FFu) c0++;
                if (ws[k] & 0xFFFF0000u) c23++;
            }
        }
        atomicAdd(&s_c0, c0);
        atomicAdd(&s_c23, c23);
        __syncthreads();
        if (tid == 0) {
            int kind;
            if (s_c0 > 0 && s_c23 == 0) kind = 0;
            else if (s_c0 == 0 && s_c23 > 0) kind = 1;
            else kind = 2;
            d_mask_kind = kind;
        }
    } else if (bid < P_GF0) {
        // ---- wfrag pack ----
        const int r48 = bid - 1;
        const int cog = r48 & 15, tap = r48 >> 4;
        for (int i = tid; i < 512; i += 256) {
            int kc = i >> 5, lane = i & 31;
            int m = cog * 16 + (lane >> 2);
            int k = kc * 16 + (lane & 3) * 2;
            uint32_t* dst = &d_wfrag[((size_t)(tap * 16 + cog) * 16 + kc) * 128 + lane * 4];
            dst[0] = pack_h2(pw[(size_t)(m * 256 + k) * 3 + tap],
                             pw[(size_t)(m * 256 + k + 1) * 3 + tap]);
            dst[1] = pack_h2(pw[(size_t)((m + 8) * 256 + k) * 3 + tap],
                             pw[(size_t)((m + 8) * 256 + k + 1) * 3 + tap]);
            dst[2] = pack_h2(pw[(size_t)(m * 256 + k + 8) * 3 + tap],
                             pw[(size_t)(m * 256 + k + 9) * 3 + tap]);
            dst[3] = pack_h2(pw[(size_t)((m + 8) * 256 + k + 8) * 3 + tap],
                             pw[(size_t)((m + 8) * 256 + k + 9) * 3 + tap]);
        }
    } else if (bid < P_XT0) {
        // ---- guide FC + gfrag pack (k-chunks of 16; 32 KB smem overlay) ----
        const int r = bid - P_GF0;           // 0..127
        const int n0 = (r & 7) * 8;
        const int b  = r >> 3;
        const int e  = tid;

        float* s_guide = dynf;               // 8*224   = 1792 floats
        float* s_gw    = dynf + 1792;        // 256*17  = 4352 floats
        float* s_g     = dynf + 1792 + 4352; // 8*256   = 2048 floats

        for (int i = tid; i < 8 * GC_; i += 256) {
            int nn = i / GC_, k = i % GC_;
            s_guide[i] = guide[((size_t)(b * N_ + n0 + nn)) * GC_ + k];
        }

        float acc[8];
#pragma unroll
        for (int nn = 0; nn < 8; nn++) acc[nn] = 0.f;

        for (int k0 = 0; k0 < GC_; k0 += 16) {
            __syncthreads();
            for (int i = tid; i < 256 * 16; i += 256) {
                int ee = i >> 4, j = i & 15;
                s_gw[ee * 17 + j] = gw[ee * GC_ + k0 + j];
            }
            __syncthreads();
#pragma unroll
            for (int j = 0; j < 16; j++) {
                float wv = s_gw[e * 17 + j];
#pragma unroll
                for (int nn = 0; nn < 8; nn++)
                    acc[nn] += s_guide[nn * GC_ + k0 + j] * wv;
            }
        }

        const float bias = gb[e];
#pragma unroll
        for (int nn = 0; nn < 8; nn++) s_g[nn * 256 + e] = acc[nn] + bias;
        __syncthreads();

        const int mg = n0 >> 4;
        const int rbase = (n0 & 8) ? 1 : 0;  // regs {1,3} vs {0,2}
        for (int i = tid; i < 512; i += 256) {
            int h = i >> 6, kc = (i >> 5) & 1, lane = i & 31;
            int nn = (lane >> 2);
            int ee = h * 32 + kc * 16 + (lane & 3) * 2;
            uint32_t* dst = &d_gfrag[(((size_t)(b * 8 + h) * 4 + mg) * 2 + kc) * 128 + lane * 4];
            dst[rbase]     = pack_h2(s_g[nn * 256 + ee],     s_g[nn * 256 + ee + 1]);
            dst[rbase + 2] = pack_h2(s_g[nn * 256 + ee + 8], s_g[nn * 256 + ee + 9]);
        }
    } else {
        // ---- xt transpose + fp16 convert ----
        float (*s)[33] = (float (*)[33])dynf;
        const int xb = bid - P_XT0;          // 0 .. 16383
        const int b = xb >> 10;
        const int ci0 = ((xb & 1023) >> 7) * 32;
        const int t0 = ((xb & 127)) * 32;
        const int tx = tid & 31, ty = tid >> 5;
#pragma unroll
        for (int k = 0; k < 4; k++)
            s[ty + 8 * k][tx] = x[((size_t)(b * CIN_ + ci0 + ty + 8 * k)) * T_ + t0 + tx];
        __syncthreads();
#pragma unroll
        for (int k = 0; k < 4; k++)
            d_xt[((size_t)b * T_ + t0 + ty + 8 * k) * CIN_ + ci0 + tx] =
                __float2half_rn(s[tx][ty + 8 * k]);
    }
}

// ---------------------------------------------------------------------------
// Kernel C: fused conv1d(k=3) + max-sigmoid attention, fp16 m16n8k16.
// REVERTED to the proven R13 version (90.0 us): CTA = 128 co x 128 t,
// warp tile 32 co x 64 t (4 cog x 2 tg), x4 tap-pairing + incremental
// addresses, two K-half cp.async pipeline, attn after conv loop.
// ---------------------------------------------------------------------------
#define CONV_ROWS   130
#define CONV_TILE_B (CONV_ROWS * 512)   // 66560 B

__global__ __launch_bounds__(256, 2) void conv_mma_kernel(
    const float* __restrict__ pb, const void* __restrict__ mask,
    const float* __restrict__ abias, float* __restrict__ out)
{
    extern __shared__ __align__(16) char s_dyn[];
    const int b = blockIdx.z, co0 = blockIdx.y * 128, t0 = blockIdx.x * 128;
    const int tid = threadIdx.x, w = tid >> 5, lane = tid & 31;
    const int cog = w & 3, tg = w >> 2;
    const int hw = blockIdx.y * 4 + cog;     // this warp's head
    const uint32_t smb = smem_u32(s_dyn);
    const __half* xtb = d_xt + (size_t)b * T_ * CIN_;

    // ---- stage half A (ci 0..127, groups 0..15) ----
#pragma unroll
    for (int it = 0; it < 9; it++) {
        int idx = tid + it * 256;            // 2080 x 16B
        if (it < 8 || idx < 2080) {
            int r = idx >> 4, g = idx & 15;
            int gt = t0 - 1 + r;
            int gtc = gt < 0 ? 0 : (gt >= T_ ? T_ - 1 : gt);
            cp16z(smb + swz512(r, g), xtb + (size_t)gtc * 256 + g * 8,
                  gt >= 0 && gt < T_);
        }
    }
    CP_COMMIT();
    // ---- stage half B (ci 128..255, groups 16..31) ----
#pragma unroll
    for (int it = 0; it < 9; it++) {
        int idx = tid + it * 256;
        if (it < 8 || idx < 2080) {
            int r = idx >> 4, g = 16 + (idx & 15);
            int gt = t0 - 1 + r;
            int gtc = gt < 0 ? 0 : (gt >= T_ ? T_ - 1 : gt);
            cp16z(smb + swz512(r, g), xtb + (size_t)gtc * 256 + g * 8,
                  gt >= 0 && gt < T_);
        }
    }
    CP_COMMIT();

    float acc[2][8][4];
#pragma unroll
    for (int mf = 0; mf < 2; mf++)
#pragma unroll
        for (int nt = 0; nt < 8; nt++)
#pragma unroll
            for (int r = 0; r < 4; r++) acc[mf][nt][r] = 0.f;

    const int lane7 = lane & 7;
    const int k_q   = (lane >> 3) & 1;   // x4: q&1 (k-group); also x2 matrix sel
    const int s_q   = (lane >> 4) & 1;   // x4: q>>1 (tap 0/1)

    // ---- compute: two K-halves, pipelined against staging ----
#pragma unroll
    for (int half = 0; half < 2; half++) {
        if (half == 0) { CP_WAIT(1); } else { CP_WAIT(0); }
        __syncthreads();
#pragma unroll 4
        for (int kcl = 0; kcl < 8; kcl++) {
            const int kc16 = half * 8 + kcl;
            uint32_t afr[2][3][4];
#pragma unroll
            for (int mf = 0; mf < 2; mf++) {
                const int cog16 = blockIdx.y * 8 + cog * 2 + mf;
#pragma unroll
                for (int tap = 0; tap < 3; tap++) {
                    const uint4 v = *(const uint4*)&d_wfrag[((size_t)(tap * 16 + cog16) * 16 + kc16) * 128 + lane * 4];
                    afr[mf][tap][0] = v.x; afr[mf][tap][1] = v.y;
                    afr[mf][tap][2] = v.z; afr[mf][tap][3] = v.w;
                }
            }
            // Incremental ldsm addresses: swizzle XOR is nt-invariant.
            uint32_t a4 = smb + swz512(tg * 64 + s_q + lane7, kc16 * 2 + k_q);
            uint32_t a2 = smb + swz512(tg * 64 + 2 + lane7,   kc16 * 2 + k_q);
#pragma unroll
            for (int nt = 0; nt < 8; nt++) {
                uint32_t q0[4], q1[2];
                ldsm_x4(q0, a4);             // {tap0 k0, tap0 k1, tap1 k0, tap1 k1}
                ldsm_x2(q1, a2);             // {tap2 k0, tap2 k1}
                a4 += 4096; a2 += 4096;
#pragma unroll
                for (int mf = 0; mf < 2; mf++) {
                    mma_f16(acc[mf][nt], afr[mf][0], q0);
                    mma_f16(acc[mf][nt], afr[mf][1], q0 + 2);
                    mma_f16(acc[mf][nt], afr[mf][2], q1);
                }
            }
        }
    }

    // ---- attention for this warp's head (tile fully resident) ----
    float attn0[8], attn1[8];
    {
        const float ab = abias[hw];
#pragma unroll
        for (int nt = 0; nt < 8; nt++) {
            float a4v[4][4];
#pragma unroll
            for (int mg = 0; mg < 4; mg++)
#pragma unroll
                for (int r = 0; r < 4; r++) a4v[mg][r] = 0.f;
#pragma unroll
            for (int kca = 0; kca < 2; kca++) {
                const int kc16 = hw * 2 + kca;
                const int gk = kc16 * 2 + k_q;
                const int r = 1 + tg * 64 + nt * 8 + lane7;
                uint32_t bfr[2];
                ldsm_x2(bfr, smb + swz512(r, gk));
#pragma unroll
                for (int mg = 0; mg < 4; mg++) {
                    const uint4 v = *(const uint4*)&d_gfrag[(((size_t)(b * 8 + hw) * 4 + mg) * 2 + kca) * 128 + lane * 4];
                    uint32_t gfr[4] = { v.x, v.y, v.z, v.w };
                    mma_f16(a4v[mg], gfr, bfr);
                }
            }
            float m0 = -1e30f, m1 = -1e30f;
#pragma unroll
            for (int mg = 0; mg < 4; mg++) {
                m0 = fmaxf(m0, fmaxf(a4v[mg][0], a4v[mg][2]));
                m1 = fmaxf(m1, fmaxf(a4v[mg][1], a4v[mg][3]));
            }
#pragma unroll
            for (int d = 4; d <= 16; d <<= 1) {
                m0 = fmaxf(m0, __shfl_xor_sync(0xffffffffu, m0, d));
                m1 = fmaxf(m1, __shfl_xor_sync(0xffffffffu, m1, d));
            }
            float z0 = m0 * 0.17677669529663687f + ab;
            float z1 = m1 * 0.17677669529663687f + ab;
            attn0[nt] = 1.f / (1.f + __expf(-z0));
            attn1[nt] = 1.f / (1.f + __expf(-z1));
        }
    }

    // ---- epilogue: (+pb) * attn * mask ----
    const int mk = d_mask_kind;
#pragma unroll
    for (int mf = 0; mf < 2; mf++) {
        const int cob = co0 + cog * 32 + mf * 16 + (lane >> 2);
        const float bias0 = pb[cob], bias1 = pb[cob + 8];
        float* o0 = out + ((size_t)(b * 256 + cob)) * T_;
        float* o1 = o0 + (size_t)8 * T_;
#pragma unroll
        for (int nt = 0; nt < 8; nt++) {
            const int t = t0 + tg * 64 + nt * 8 + 2 * (lane & 3);
            float m0 = mask_at(mask, mk, b, t);
            float m1 = mask_at(mask, mk, b, t + 1);
            float2 v0, v1;
            v0.x = (acc[mf][nt][0] + bias0) * attn0[nt] * m0;
            v0.y = (acc[mf][nt][1] + bias0) * attn1[nt] * m1;
            v1.x = (acc[mf][nt][2] + bias1) * attn0[nt] * m0;
            v1.y = (acc[mf][nt][3] + bias1) * attn1[nt] * m1;
            *(float2*)(o0 + t) = v0;
            *(float2*)(o1 + t) = v1;
        }
    }
}

// ---------------------------------------------------------------------------
extern "C" void kernel_launch(void* const* d_in, const int* in_sizes, int n_in,
                              void* d_out, int out_size)
{
    const float* x     = (const float*)d_in[0];
    const float* guide = (const float*)d_in[1];
    const void*  mask  = (const void*)d_in[2];
    const float* gw    = (const float*)d_in[3];
    const float* gb    = (const float*)d_in[4];
    const float* abias = (const float*)d_in[5];
    const float* pw    = (const float*)d_in[6];
    const float* pb    = (const float*)d_in[7];
    float*       out   = (float*)d_out;

    static int attr_done = 0;
    if (!attr_done) {
        cudaFuncSetAttribute(conv_mma_kernel,
                             cudaFuncAttributeMaxDynamicSharedMemorySize, CONV_TILE_B);
        attr_done = 1;
    }

    prep_kernel<<<P_XT0 + 16384, 256, 32768>>>(
        x, pw, guide, gw, gb, (const uint4*)mask, in_sizes[2] / 16);
    conv_mma_kernel<<<dim3(T_ / 128, COUT_ / 128, B_), 256, CONV_TILE_B>>>(pb, mask, abias, out);
}

// round 17
// speedup vs baseline: 1.2802x; 1.0164x over previous
#include <cuda_runtime.h>
#include <cuda_fp16.h>
#include <cstdint>

// Problem constants
#define B_    16
#define CIN_  256
#define T_    4096
#define N_    64
#define GC_   224
#define EC_   256
#define H_    8
#define HC_   32
#define COUT_ 256

// Scratch (no cudaMalloc allowed)
__device__ __half d_xt[(size_t)B_ * T_ * CIN_];       // x^T as fp16 [b][t][ci] (32 MB)
__device__ uint32_t d_wfrag[3 * 16 * 16 * 128];       // fp16x2 A-frags, conv
__device__ uint32_t d_gfrag[16 * 8 * 4 * 2 * 128];    // fp16x2 A-frags, attn
__device__ int    d_mask_kind;                        // 0=int32, 1=float32, 2=byte

// ---------------------------------------------------------------------------
// Helpers (base sm_100-legal: mma.sync sm_80+, ldmatrix sm_75+, cp.async sm_80+)
// ---------------------------------------------------------------------------
__device__ __forceinline__ uint32_t smem_u32(const void* p) {
    uint32_t a;
    asm("{ .reg .u64 t; cvta.to.shared.u64 t, %1; cvt.u32.u64 %0, t; }"
        : "=r"(a) : "l"(p));
    return a;
}
__device__ __forceinline__ uint32_t pack_h2(float lo, float hi) {
    __half2 h = __floats2half2_rn(lo, hi);   // .x = lo (lower 16 bits)
    return *(uint32_t*)&h;
}
__device__ __forceinline__ void ldsm_x2(uint32_t* r, uint32_t addr) {
    asm volatile("ldmatrix.sync.aligned.m8n8.x2.shared.b16 {%0, %1}, [%2];"
                 : "=r"(r[0]), "=r"(r[1]) : "r"(addr));
}
__device__ __forceinline__ void ldsm_x4(uint32_t* r, uint32_t addr) {
    asm volatile("ldmatrix.sync.aligned.m8n8.x4.shared.b16 {%0, %1, %2, %3}, [%4];"
                 : "=r"(r[0]), "=r"(r[1]), "=r"(r[2]), "=r"(r[3]) : "r"(addr));
}
__device__ __forceinline__ void mma_f16(float* d, const uint32_t* a, const uint32_t* b) {
    asm volatile(
        "mma.sync.aligned.m16n8k16.row.col.f32.f16.f16.f32 "
        "{%0,%1,%2,%3}, {%4,%5,%6,%7}, {%8,%9}, {%0,%1,%2,%3};"
        : "+f"(d[0]), "+f"(d[1]), "+f"(d[2]), "+f"(d[3])
        : "r"(a[0]), "r"(a[1]), "r"(a[2]), "r"(a[3]), "r"(b[0]), "r"(b[1]));
}
// cp.async 16B with zero-fill when invalid (src-size = 0)
__device__ __forceinline__ void cp16z(uint32_t dst, const void* src, bool valid) {
    int sz = valid ? 16 : 0;
    asm volatile("cp.async.cg.shared.global [%0], [%1], 16, %2;"
                 :: "r"(dst), "l"(src), "r"(sz) : "memory");
}
#define CP_COMMIT() asm volatile("cp.async.commit_group;" ::: "memory")
#define CP_WAIT(n)  asm volatile("cp.async.wait_group %0;" :: "n"(n) : "memory")

// Swizzled 512B-row tile (32 groups of 16B per row): logical group g stored at
// (g&24) | ((g&7) ^ (r&7)).
__device__ __forceinline__ uint32_t swz512(int r, int g) {
    return (uint32_t)(r * 512 + (((g & 24) | ((g & 7) ^ (r & 7))) << 4));
}

__device__ __forceinline__ float mask_at(const void* mp, int kind, int b, int t)
{
    size_t idx = (size_t)b * T_ + t;
    if (kind == 0)      return ((const int*)mp)[idx]   != 0   ? 1.f : 0.f;
    else if (kind == 1) return ((const float*)mp)[idx] != 0.f ? 1.f : 0.f;
    else                return ((const unsigned char*)mp)[idx] ? 1.f : 0.f;
}

// ---------------------------------------------------------------------------
// Kernel P: ALL prep in one launch, role-dispatched by blockIdx.x (proven R16):
//   bid 0         : mask classify
//   bid 1..48     : wfrag pack
//   bid 49..176   : guide FC + gfrag pack (32 KB dyn smem overlay)
//   bid 177..     : xt transpose + fp16
// ---------------------------------------------------------------------------
#define P_GF0 49
#define P_XT0 177
__global__ __launch_bounds__(256) void prep_kernel(
    const float* __restrict__ x, const float* __restrict__ pw,
    const float* __restrict__ guide, const float* __restrict__ gw,
    const float* __restrict__ gb,
    const uint4* __restrict__ m16, int n16)
{
    extern __shared__ __align__(16) float dynf[];
    const int bid = blockIdx.x, tid = threadIdx.x;

    if (bid == 0) {
        // ---- mask classify ----
        __shared__ int s_c0, s_c23;
        if (tid == 0) { s_c0 = 0; s_c23 = 0; }
        __syncthreads();
        int c0 = 0, c23 = 0;
        for (int i = tid; i < n16; i += 256) {
            uint4 v = m16[i];
            uint32_t ws[4] = { v.x, v.y, v.z, v.w };
#pragma unroll
            for (int k = 0; k < 4; k++) {
                if (ws[k] & 0x000000FFu) c0++;
                if (ws[k] & 0xFFFF0000u) c23++;
            }
        }
        atomicAdd(&s_c0, c0);
        atomicAdd(&s_c23, c23);
        __syncthreads();
        if (tid == 0) {
            int kind;
            if (s_c0 > 0 && s_c23 == 0) kind = 0;
            else if (s_c0 == 0 && s_c23 > 0) kind = 1;
            else kind = 2;
            d_mask_kind = kind;
        }
    } else if (bid < P_GF0) {
        // ---- wfrag pack ----
        const int r48 = bid - 1;
        const int cog = r48 & 15, tap = r48 >> 4;
        for (int i = tid; i < 512; i += 256) {
            int kc = i >> 5, lane = i & 31;
            int m = cog * 16 + (lane >> 2);
            int k = kc * 16 + (lane & 3) * 2;
            uint32_t* dst = &d_wfrag[((size_t)(tap * 16 + cog) * 16 + kc) * 128 + lane * 4];
            dst[0] = pack_h2(pw[(size_t)(m * 256 + k) * 3 + tap],
                             pw[(size_t)(m * 256 + k + 1) * 3 + tap]);
            dst[1] = pack_h2(pw[(size_t)((m + 8) * 256 + k) * 3 + tap],
                             pw[(size_t)((m + 8) * 256 + k + 1) * 3 + tap]);
            dst[2] = pack_h2(pw[(size_t)(m * 256 + k + 8) * 3 + tap],
                             pw[(size_t)(m * 256 + k + 9) * 3 + tap]);
            dst[3] = pack_h2(pw[(size_t)((m + 8) * 256 + k + 8) * 3 + tap],
                             pw[(size_t)((m + 8) * 256 + k + 9) * 3 + tap]);
        }
    } else if (bid < P_XT0) {
        // ---- guide FC + gfrag pack ----
        const int r = bid - P_GF0;           // 0..127
        const int n0 = (r & 7) * 8;
        const int b  = r >> 3;
        const int e  = tid;

        float* s_guide = dynf;               // 8*224   = 1792 floats
        float* s_gw    = dynf + 1792;        // 256*17  = 4352 floats
        float* s_g     = dynf + 1792 + 4352; // 8*256   = 2048 floats

        for (int i = tid; i < 8 * GC_; i += 256) {
            int nn = i / GC_, k = i % GC_;
            s_guide[i] = guide[((size_t)(b * N_ + n0 + nn)) * GC_ + k];
        }

        float acc[8];
#pragma unroll
        for (int nn = 0; nn < 8; nn++) acc[nn] = 0.f;

        for (int k0 = 0; k0 < GC_; k0 += 16) {
            __syncthreads();
            for (int i = tid; i < 256 * 16; i += 256) {
                int ee = i >> 4, j = i & 15;
                s_gw[ee * 17 + j] = gw[ee * GC_ + k0 + j];
            }
            __syncthreads();
#pragma unroll
            for (int j = 0; j < 16; j++) {
                float wv = s_gw[e * 17 + j];
#pragma unroll
                for (int nn = 0; nn < 8; nn++)
                    acc[nn] += s_guide[nn * GC_ + k0 + j] * wv;
            }
        }

        const float bias = gb[e];
#pragma unroll
        for (int nn = 0; nn < 8; nn++) s_g[nn * 256 + e] = acc[nn] + bias;
        __syncthreads();

        const int mg = n0 >> 4;
        const int rbase = (n0 & 8) ? 1 : 0;  // regs {1,3} vs {0,2}
        for (int i = tid; i < 512; i += 256) {
            int h = i >> 6, kc = (i >> 5) & 1, lane = i & 31;
            int nn = (lane >> 2);
            int ee = h * 32 + kc * 16 + (lane & 3) * 2;
            uint32_t* dst = &d_gfrag[(((size_t)(b * 8 + h) * 4 + mg) * 2 + kc) * 128 + lane * 4];
            dst[rbase]     = pack_h2(s_g[nn * 256 + ee],     s_g[nn * 256 + ee + 1]);
            dst[rbase + 2] = pack_h2(s_g[nn * 256 + ee + 8], s_g[nn * 256 + ee + 9]);
        }
    } else {
        // ---- xt transpose + fp16 convert ----
        float (*s)[33] = (float (*)[33])dynf;
        const int xb = bid - P_XT0;          // 0 .. 16383
        const int b = xb >> 10;
        const int ci0 = ((xb & 1023) >> 7) * 32;
        const int t0 = ((xb & 127)) * 32;
        const int tx = tid & 31, ty = tid >> 5;
#pragma unroll
        for (int k = 0; k < 4; k++)
            s[ty + 8 * k][tx] = x[((size_t)(b * CIN_ + ci0 + ty + 8 * k)) * T_ + t0 + tx];
        __syncthreads();
#pragma unroll
        for (int k = 0; k < 4; k++)
            d_xt[((size_t)b * T_ + t0 + ty + 8 * k) * CIN_ + ci0 + tx] =
                __float2half_rn(s[tx][ty + 8 * k]);
    }
}

// ---------------------------------------------------------------------------
// Kernel C: fused conv1d(k=3) + max-sigmoid attention, fp16 m16n8k16.
// R16 structure, with the mainloop reordered so consecutive MMAs hit 4
// DISTINCT accumulators (nt processed in pairs, tap-outer order): same-acc
// reuse distance = 4 instructions, covering the HMMA accumulator RAW latency.
// ---------------------------------------------------------------------------
#define CONV_ROWS   130
#define CONV_TILE_B (CONV_ROWS * 512)   // 66560 B

__global__ __launch_bounds__(256, 2) void conv_mma_kernel(
    const float* __restrict__ pb, const void* __restrict__ mask,
    const float* __restrict__ abias, float* __restrict__ out)
{
    extern __shared__ __align__(16) char s_dyn[];
    const int b = blockIdx.z, co0 = blockIdx.y * 128, t0 = blockIdx.x * 128;
    const int tid = threadIdx.x, w = tid >> 5, lane = tid & 31;
    const int cog = w & 3, tg = w >> 2;
    const int hw = blockIdx.y * 4 + cog;     // this warp's head
    const uint32_t smb = smem_u32(s_dyn);
    const __half* xtb = d_xt + (size_t)b * T_ * CIN_;

    // ---- stage half A (ci 0..127, groups 0..15) ----
#pragma unroll
    for (int it = 0; it < 9; it++) {
        int idx = tid + it * 256;            // 2080 x 16B
        if (it < 8 || idx < 2080) {
            int r = idx >> 4, g = idx & 15;
            int gt = t0 - 1 + r;
            int gtc = gt < 0 ? 0 : (gt >= T_ ? T_ - 1 : gt);
            cp16z(smb + swz512(r, g), xtb + (size_t)gtc * 256 + g * 8,
                  gt >= 0 && gt < T_);
        }
    }
    CP_COMMIT();
    // ---- stage half B (ci 128..255, groups 16..31) ----
#pragma unroll
    for (int it = 0; it < 9; it++) {
        int idx = tid + it * 256;
        if (it < 8 || idx < 2080) {
            int r = idx >> 4, g = 16 + (idx & 15);
            int gt = t0 - 1 + r;
            int gtc = gt < 0 ? 0 : (gt >= T_ ? T_ - 1 : gt);
            cp16z(smb + swz512(r, g), xtb + (size_t)gtc * 256 + g * 8,
                  gt >= 0 && gt < T_);
        }
    }
    CP_COMMIT();

    float acc[2][8][4];
#pragma unroll
    for (int mf = 0; mf < 2; mf++)
#pragma unroll
        for (int nt = 0; nt < 8; nt++)
#pragma unroll
            for (int r = 0; r < 4; r++) acc[mf][nt][r] = 0.f;

    const int lane7 = lane & 7;
    const int k_q   = (lane >> 3) & 1;   // x4: q&1 (k-group); also x2 matrix sel
    const int s_q   = (lane >> 4) & 1;   // x4: q>>1 (tap 0/1)

    // ---- compute: two K-halves, pipelined against staging ----
#pragma unroll
    for (int half = 0; half < 2; half++) {
        if (half == 0) { CP_WAIT(1); } else { CP_WAIT(0); }
        __syncthreads();
#pragma unroll 4
        for (int kcl = 0; kcl < 8; kcl++) {
            const int kc16 = half * 8 + kcl;
            uint32_t afr[2][3][4];
#pragma unroll
            for (int mf = 0; mf < 2; mf++) {
                const int cog16 = blockIdx.y * 8 + cog * 2 + mf;
#pragma unroll
                for (int tap = 0; tap < 3; tap++) {
                    const uint4 v = *(const uint4*)&d_wfrag[((size_t)(tap * 16 + cog16) * 16 + kc16) * 128 + lane * 4];
                    afr[mf][tap][0] = v.x; afr[mf][tap][1] = v.y;
                    afr[mf][tap][2] = v.z; afr[mf][tap][3] = v.w;
                }
            }
            // Incremental ldsm addresses: swizzle XOR is nt-invariant.
            uint32_t a4 = smb + swz512(tg * 64 + s_q + lane7, kc16 * 2 + k_q);
            uint32_t a2 = smb + swz512(tg * 64 + 2 + lane7,   kc16 * 2 + k_q);
#pragma unroll
            for (int ntp = 0; ntp < 4; ntp++) {
                // Load B-fragments for a PAIR of nt (4 independent acc chains).
                uint32_t bfr[2][6];
#pragma unroll
                for (int nn = 0; nn < 2; nn++) {
                    ldsm_x4(bfr[nn], a4);        // {tap0 k0, tap0 k1, tap1 k0, tap1 k1}
                    ldsm_x2(bfr[nn] + 4, a2);    // {tap2 k0, tap2 k1}
                    a4 += 4096; a2 += 4096;
                }
                // tap-outer order: consecutive MMAs hit 4 distinct accumulators.
#pragma unroll
                for (int tap = 0; tap < 3; tap++)
#pragma unroll
                    for (int nn = 0; nn < 2; nn++)
#pragma unroll
                        for (int mf = 0; mf < 2; mf++)
                            mma_f16(acc[mf][ntp * 2 + nn], afr[mf][tap], bfr[nn] + 2 * tap);
            }
        }
    }

    // ---- attention for this warp's head (tile fully resident) ----
    float attn0[8], attn1[8];
    {
        const float ab = abias[hw];
#pragma unroll
        for (int nt = 0; nt < 8; nt++) {
            float a4v[4][4];
#pragma unroll
            for (int mg = 0; mg < 4; mg++)
#pragma unroll
                for (int r = 0; r < 4; r++) a4v[mg][r] = 0.f;
#pragma unroll
            for (int kca = 0; kca < 2; kca++) {
                const int kc16 = hw * 2 + kca;
                const int gk = kc16 * 2 + k_q;
                const int r = 1 + tg * 64 + nt * 8 + lane7;
                uint32_t bfr[2];
                ldsm_x2(bfr, smb + swz512(r, gk));
#pragma unroll
                for (int mg = 0; mg < 4; mg++) {
                    const uint4 v = *(const uint4*)&d_gfrag[(((size_t)(b * 8 + hw) * 4 + mg) * 2 + kca) * 128 + lane * 4];
                    uint32_t gfr[4] = { v.x, v.y, v.z, v.w };
                    mma_f16(a4v[mg], gfr, bfr);
                }
            }
            float m0 = -1e30f, m1 = -1e30f;
#pragma unroll
            for (int mg = 0; mg < 4; mg++) {
                m0 = fmaxf(m0, fmaxf(a4v[mg][0], a4v[mg][2]));
                m1 = fmaxf(m1, fmaxf(a4v[mg][1], a4v[mg][3]));
            }
#pragma unroll
            for (int d = 4; d <= 16; d <<= 1) {
                m0 = fmaxf(m0, __shfl_xor_sync(0xffffffffu, m0, d));
                m1 = fmaxf(m1, __shfl_xor_sync(0xffffffffu, m1, d));
            }
            float z0 = m0 * 0.17677669529663687f + ab;
            float z1 = m1 * 0.17677669529663687f + ab;
            attn0[nt] = 1.f / (1.f + __expf(-z0));
            attn1[nt] = 1.f / (1.f + __expf(-z1));
        }
    }

    // ---- epilogue: (+pb) * attn * mask ----
    const int mk = d_mask_kind;
#pragma unroll
    for (int mf = 0; mf < 2; mf++) {
        const int cob = co0 + cog * 32 + mf * 16 + (lane >> 2);
        const float bias0 = pb[cob], bias1 = pb[cob + 8];
        float* o0 = out + ((size_t)(b * 256 + cob)) * T_;
        float* o1 = o0 + (size_t)8 * T_;
#pragma unroll
        for (int nt = 0; nt < 8; nt++) {
            const int t = t0 + tg * 64 + nt * 8 + 2 * (lane & 3);
            float m0 = mask_at(mask, mk, b, t);
            float m1 = mask_at(mask, mk, b, t + 1);
            float2 v0, v1;
            v0.x = (acc[mf][nt][0] + bias0) * attn0[nt] * m0;
            v0.y = (acc[mf][nt][1] + bias0) * attn1[nt] * m1;
            v1.x = (acc[mf][nt][2] + bias1) * attn0[nt] * m0;
            v1.y = (acc[mf][nt][3] + bias1) * attn1[nt] * m1;
            *(float2*)(o0 + t) = v0;
            *(float2*)(o1 + t) = v1;
        }
    }
}

// ---------------------------------------------------------------------------
extern "C" void kernel_launch(void* const* d_in, const int* in_sizes, int n_in,
                              void* d_out, int out_size)
{
    const float* x     = (const float*)d_in[0];
    const float* guide = (const float*)d_in[1];
    const void*  mask  = (const void*)d_in[2];
    const float* gw    = (const float*)d_in[3];
    const float* gb    = (const float*)d_in[4];
    const float* abias = (const float*)d_in[5];
    const float* pw    = (const float*)d_in[6];
    const float* pb    = (const float*)d_in[7];
    float*       out   = (float*)d_out;

    static int attr_done = 0;
    if (!attr_done) {
        cudaFuncSetAttribute(conv_mma_kernel,
                             cudaFuncAttributeMaxDynamicSharedMemorySize, CONV_TILE_B);
        attr_done = 1;
    }

    prep_kernel<<<P_XT0 + 16384, 256, 32768>>>(
        x, pw, guide, gw, gb, (const uint4*)mask, in_sizes[2] / 16);
    conv_mma_kernel<<<dim3(T_ / 128, COUT_ / 128, B_), 256, CONV_TILE_B>>>(pb, mask, abias, out);
}